// round 10
// baseline (speedup 1.0000x reference)
#include <cuda_runtime.h>
#include <cuda_bf16.h>
#include <cstdint>

#define BB 32
#define CC 512
#define NN 1024
#define CQ 64
#define MR 640

// ---------------- scratch (device globals; no cudaMalloc) ----------------
__device__ float g_scale[3];
__device__ float g_bcat[MR];
__device__ __align__(16) __nv_bfloat16 g_w2h[MR * CC];
__device__ __align__(16) __nv_bfloat16 g_w2l[MR * CC];
__device__ __align__(16) __nv_bfloat16 g_xTh[(size_t)BB * NN * CC];
__device__ __align__(16) __nv_bfloat16 g_xTl[(size_t)BB * NN * CC];
__device__ __align__(16) __nv_bfloat16 g_qTh[(size_t)BB * NN * CQ];
__device__ __align__(16) __nv_bfloat16 g_qTl[(size_t)BB * NN * CQ];
__device__ __align__(16) __nv_bfloat16 g_kTh[(size_t)BB * NN * CQ];
__device__ __align__(16) __nv_bfloat16 g_kTl[(size_t)BB * NN * CQ];
__device__ __align__(16) __nv_bfloat16 g_vh [(size_t)BB * CC * NN];
__device__ __align__(16) __nv_bfloat16 g_vl [(size_t)BB * CC * NN];
__device__ __align__(16) __nv_bfloat16 g_pTh[(size_t)BB * NN * NN];
__device__ float g_csum[BB * NN];
__device__ float g_cinv[BB * NN];

// ---------------- helpers ----------------
__device__ __forceinline__ uint32_t smem_u32(const void* p) {
    uint32_t a;
    asm("{ .reg .u64 t; cvta.to.shared.u64 t, %1; cvt.u32.u64 %0, t; }" : "=r"(a) : "l"(p));
    return a;
}
__device__ __forceinline__ void cp16(uint32_t s, const void* g) {
    asm volatile("cp.async.cg.shared.global [%0], [%1], 16;" :: "r"(s), "l"(g));
}
__device__ __forceinline__ void cp_commit() { asm volatile("cp.async.commit_group;" ::: "memory"); }
__device__ __forceinline__ void cp_wait1()  { asm volatile("cp.async.wait_group 1;" ::: "memory"); }
__device__ __forceinline__ void cp_wait0()  { asm volatile("cp.async.wait_group 0;" ::: "memory"); }

__device__ __forceinline__ void ldsm4(uint32_t r[4], uint32_t addr) {
    asm volatile("ldmatrix.sync.aligned.m8n8.x4.shared.b16 {%0,%1,%2,%3}, [%4];"
        : "=r"(r[0]), "=r"(r[1]), "=r"(r[2]), "=r"(r[3]) : "r"(addr));
}

__device__ __forceinline__ void mma16816(float* c, const uint32_t a[4], uint32_t b0, uint32_t b1) {
    asm volatile(
        "mma.sync.aligned.m16n8k16.row.col.f32.bf16.bf16.f32 "
        "{%0,%1,%2,%3}, {%4,%5,%6,%7}, {%8,%9}, {%0,%1,%2,%3};"
        : "+f"(c[0]), "+f"(c[1]), "+f"(c[2]), "+f"(c[3])
        : "r"(a[0]), "r"(a[1]), "r"(a[2]), "r"(a[3]), "r"(b0), "r"(b1));
}

__device__ __forceinline__ void split2(float f, __nv_bfloat16& h, __nv_bfloat16& l) {
    h = __float2bfloat16(f);
    l = __float2bfloat16(f - __bfloat162float(h));
}
__device__ __forceinline__ uint32_t packbf(__nv_bfloat16 a, __nv_bfloat16 b) {
    __nv_bfloat162 t(a, b);
    return *reinterpret_cast<uint32_t*>(&t);
}

// ---------------- GEMM core: CTA tile 128(M) x 256(N), K-chunk 32 ----------------
// smem per stage: Ah(128x80B) Al(128x80B) Bh(256x80B) [Bl(256x80B)]
// stride-80 rows -> conflict-free LDSM (banks r*20%32 all distinct per 8 rows).
#define OFF_AL 10240u
#define OFF_BH 20480u
#define OFF_BL 40960u
#define STG3   61440u
#define STG2   40960u
#define SMEM_P3 (2u * STG3)   // 122880
#define SMEM_P2 (2u * STG2)   //  81920

template<bool BL>
__device__ __forceinline__ void issue_chunk(uint32_t su, int stage,
        const __nv_bfloat16* Ah, const __nv_bfloat16* Al, int lda,
        const __nv_bfloat16* Bh, const __nv_bfloat16* Bl, int ldb,
        int koff, int tid) {
    const uint32_t STG = BL ? STG3 : STG2;
    uint32_t sb = su + (uint32_t)stage * STG;
    const __nv_bfloat16* As[2] = { Ah, Al };
    #pragma unroll
    for (int a = 0; a < 2; a++) {
        uint32_t ab = sb + (uint32_t)a * OFF_AL;
        #pragma unroll
        for (int i = 0; i < 2; i++) {
            int idx = tid + 256 * i;
            int row = idx >> 2, seg = idx & 3;
            cp16(ab + (uint32_t)(row * 80 + seg * 16),
                 As[a] + (size_t)row * lda + koff + seg * 8);
        }
    }
    const __nv_bfloat16* Bs[2] = { Bh, Bl };
    const int NB = BL ? 2 : 1;
    #pragma unroll
    for (int a = 0; a < NB; a++) {
        uint32_t bb = sb + OFF_BH + (uint32_t)a * 20480u;
        #pragma unroll
        for (int i = 0; i < 4; i++) {
            int idx = tid + 256 * i;
            int row = idx >> 2, seg = idx & 3;
            cp16(bb + (uint32_t)(row * 80 + seg * 16),
                 Bs[a] + (size_t)row * ldb + koff + seg * 8);
        }
    }
    cp_commit();
}

template<bool BL>
__device__ __forceinline__ void compute_chunk(uint32_t su, int stage,
        int wm, int wn, int lane, float acc[4][8][4]) {
    const uint32_t STG = BL ? STG3 : STG2;
    uint32_t sb = su + (uint32_t)stage * STG;
    int j = lane >> 3, r7 = lane & 7;
    uint32_t Ab = sb + (uint32_t)((wm * 64 + (j & 1) * 8 + r7) * 80 + (j >> 1) * 16);
    uint32_t Bb = sb + OFF_BH + (uint32_t)((wn * 64 + (j >> 1) * 8 + r7) * 80 + (j & 1) * 16);
    #pragma unroll
    for (int kk = 0; kk < 2; kk++) {
        uint32_t ko = (uint32_t)(kk * 32);
        uint32_t ah[4][4], al[4][4];
        #pragma unroll
        for (int mt = 0; mt < 4; mt++) ldsm4(ah[mt], Ab + (uint32_t)(mt * 1280) + ko);
        #pragma unroll
        for (int mt = 0; mt < 4; mt++) ldsm4(al[mt], Ab + OFF_AL + (uint32_t)(mt * 1280) + ko);
        #pragma unroll
        for (int half = 0; half < 2; half++) {
            uint32_t bh[2][4], bl[2][4];
            #pragma unroll
            for (int p = 0; p < 2; p++) ldsm4(bh[p], Bb + (uint32_t)((half * 2 + p) * 1280) + ko);
            if (BL) {
                #pragma unroll
                for (int p = 0; p < 2; p++) ldsm4(bl[p], Bb + 20480u + (uint32_t)((half * 2 + p) * 1280) + ko);
            }
            #pragma unroll
            for (int mt = 0; mt < 4; mt++)
                #pragma unroll
                for (int ntl = 0; ntl < 4; ntl++) {
                    int np = ntl >> 1, o = (ntl & 1) * 2;
                    float* C = acc[mt][half * 4 + ntl];
                    mma16816(C, ah[mt], bh[np][o], bh[np][o + 1]);
                    mma16816(C, al[mt], bh[np][o], bh[np][o + 1]);
                    if (BL) mma16816(C, ah[mt], bl[np][o], bl[np][o + 1]);
                }
        }
    }
}

template<bool BL>
__device__ __forceinline__ void run_gemm(uint32_t su,
        const __nv_bfloat16* Ah, const __nv_bfloat16* Al, int lda,
        const __nv_bfloat16* Bh, const __nv_bfloat16* Bl, int ldb,
        int nch, float acc[4][8][4]) {
    int tid = threadIdx.x, lane = tid & 31, wid = tid >> 5;
    int wm = wid >> 2, wn = wid & 3;
    #pragma unroll
    for (int i = 0; i < 4; i++)
        #pragma unroll
        for (int j = 0; j < 8; j++)
            #pragma unroll
            for (int e = 0; e < 4; e++) acc[i][j][e] = 0.f;

    issue_chunk<BL>(su, 0, Ah, Al, lda, Bh, Bl, ldb, 0, tid);
    issue_chunk<BL>(su, 1, Ah, Al, lda, Bh, Bl, ldb, 32, tid);
    for (int ch = 0; ch < nch; ch++) {
        if (ch == nch - 1) cp_wait0(); else cp_wait1();
        __syncthreads();
        compute_chunk<BL>(su, ch & 1, wm, wn, lane, acc);
        __syncthreads();
        if (ch + 2 < nch)
            issue_chunk<BL>(su, ch & 1, Ah, Al, lda, Bh, Bl, ldb, (ch + 2) * 32, tid);
    }
}

// Stage 64-row half h of the 128x256 fp32 result into fb (stride 264 floats).
__device__ __forceinline__ void stage_rows(float* fb, int h, float acc[4][8][4],
                                           int wm, int wn, int lane) {
    if (wm != h) return;
    int g = lane >> 2, t = lane & 3;
    #pragma unroll
    for (int mt = 0; mt < 4; mt++)
        #pragma unroll
        for (int nt = 0; nt < 8; nt++) {
            float* p = fb + (mt * 16 + g) * 264 + wn * 64 + nt * 8 + 2 * t;
            p[0] = acc[mt][nt][0]; p[1] = acc[mt][nt][1];
            p[8 * 264] = acc[mt][nt][2]; p[8 * 264 + 1] = acc[mt][nt][3];
        }
}

// =================================================================
// Spectral norm (fp32)
// =================================================================
__global__ void spectral_k(const float* __restrict__ Wq, const float* __restrict__ uq,
                           const float* __restrict__ Wk, const float* __restrict__ uk,
                           const float* __restrict__ Wv, const float* __restrict__ uv) {
    const float* W; const float* u; int out;
    if (blockIdx.x == 0)      { W = Wq; u = uq; out = CQ; }
    else if (blockIdx.x == 1) { W = Wk; u = uk; out = CQ; }
    else                      { W = Wv; u = uv; out = CC; }
    const int in = CC;
    __shared__ float sv[CC];
    __shared__ float st[CC];
    __shared__ float red[16];
    int tid = threadIdx.x, lane = tid & 31, w = tid >> 5;

    float acc = 0.f;
    for (int i = 0; i < out; i++) acc += W[i * in + tid] * u[i];
    sv[tid] = acc;

    float s = acc * acc;
    #pragma unroll
    for (int o = 16; o; o >>= 1) s += __shfl_xor_sync(0xffffffffu, s, o);
    if (lane == 0) red[w] = s;
    __syncthreads();
    if (tid < 16) {
        float r = red[tid];
        #pragma unroll
        for (int o = 8; o; o >>= 1) r += __shfl_xor_sync(0xffffu, r, o);
        if (tid == 0) red[0] = r;
    }
    __syncthreads();
    float inv = rsqrtf(red[0]);
    __syncthreads();

    for (int i = w; i < out; i += 16) {
        float a = 0.f;
        for (int jj = lane; jj < in; jj += 32) a += W[i * in + jj] * sv[jj];
        #pragma unroll
        for (int o = 16; o; o >>= 1) a += __shfl_xor_sync(0xffffffffu, a, o);
        if (lane == 0) st[i] = a * inv;
    }
    __syncthreads();

    float q = (tid < out) ? st[tid] * st[tid] : 0.f;
    #pragma unroll
    for (int o = 16; o; o >>= 1) q += __shfl_xor_sync(0xffffffffu, q, o);
    if (lane == 0) red[w] = q;
    __syncthreads();
    if (tid == 0) {
        float r = 0.f;
        #pragma unroll
        for (int i = 0; i < 16; i++) r += red[i];
        g_scale[blockIdx.x] = rsqrtf(r);
    }
}

// =================================================================
// Scaled concatenated weights -> bf16 hi/lo + fp32 bias; also zero csum
// =================================================================
__global__ void build_w2k(const float* __restrict__ Wq, const float* __restrict__ bq,
                          const float* __restrict__ Wk, const float* __restrict__ bk,
                          const float* __restrict__ Wv, const float* __restrict__ bv) {
    int idx = blockIdx.x * blockDim.x + threadIdx.x;
    if (idx >= MR * CC) return;
    if (idx < BB * NN) g_csum[idx] = 0.f;
    int r = idx >> 9, c = idx & (CC - 1);
    float wv, sc;
    if (r < CQ)          { wv = Wq[r * CC + c];            sc = g_scale[0]; }
    else if (r < 2 * CQ) { wv = Wk[(r - CQ) * CC + c];     sc = g_scale[1]; }
    else                 { wv = Wv[(r - 2 * CQ) * CC + c]; sc = g_scale[2]; }
    __nv_bfloat16 h, l;
    split2(wv * sc, h, l);
    g_w2h[idx] = h; g_w2l[idx] = l;
    if (c == 0)
        g_bcat[r] = (r < CQ) ? bq[r] : (r < 2 * CQ ? bk[r - CQ] : bv[r - 2 * CQ]);
}

// =================================================================
// Transpose+split x: [b][c][n] fp32 -> xT hi/lo bf16 [b][n][c]
// =================================================================
__global__ void xsplit_k(const float* __restrict__ x) {
    __shared__ float t[32][33];
    int b = blockIdx.z, n0 = blockIdx.x * 32, c0 = blockIdx.y * 32;
    int tx = threadIdx.x, ty = threadIdx.y;   // 32 x 8
    const float* xb = x + (size_t)b * CC * NN;
    #pragma unroll
    for (int j = 0; j < 4; j++)
        t[ty + 8 * j][tx] = xb[(size_t)(c0 + ty + 8 * j) * NN + n0 + tx];
    __syncthreads();
    #pragma unroll
    for (int j = 0; j < 4; j++) {
        int n = n0 + ty + 8 * j;
        __nv_bfloat16 h, l;
        split2(t[tx][ty + 8 * j], h, l);
        size_t o = ((size_t)b * NN + n) * CC + c0 + tx;
        g_xTh[o] = h; g_xTl[o] = l;
    }
}

// =================================================================
// Unified proj: D[r][n] = wcat[r]·xT[n] over r-block (by*128), n-block (bx*256)
//  by==0  -> rows are q(0..63)/k(64..127): transposed epilogue -> qT/kT [b][n][64]
//  by>=1  -> rows are v channels: direct epilogue -> v hi/lo [b][c][n]
// =================================================================
__global__ __launch_bounds__(256, 1)
void proj_mma(void) {
    extern __shared__ __align__(16) char sm[];
    uint32_t su = smem_u32(sm);
    int b = blockIdx.z, n0 = blockIdx.x * 256, r0 = blockIdx.y * 128;
    const __nv_bfloat16* Ah = g_w2h + (size_t)r0 * CC;
    const __nv_bfloat16* Al = g_w2l + (size_t)r0 * CC;
    const __nv_bfloat16* Bh = g_xTh + ((size_t)b * NN + n0) * CC;
    const __nv_bfloat16* Bl = g_xTl + ((size_t)b * NN + n0) * CC;
    float acc[4][8][4];
    run_gemm<true>(su, Ah, Al, CC, Bh, Bl, CC, CC / 32, acc);

    int tid = threadIdx.x, lane = tid & 31, wid = tid >> 5;
    int wm = wid >> 2, wn = wid & 3;
    float* fb = (float*)sm;

    if (blockIdx.y == 0) {
        // transposed epilogue: fbT[128 n][132] per n-half
        int g = lane >> 2, t = lane & 3;
        for (int nh = 0; nh < 2; nh++) {
            __syncthreads();
            if ((wn >> 1) == nh) {
                int nbase = (wn & 1) * 64;
                #pragma unroll
                for (int mt = 0; mt < 4; mt++)
                    #pragma unroll
                    for (int nt = 0; nt < 8; nt++) {
                        int nl = nbase + nt * 8 + 2 * t;
                        int r  = wm * 64 + mt * 16 + g;
                        fb[nl * 132 + r]           = acc[mt][nt][0];
                        fb[(nl + 1) * 132 + r]     = acc[mt][nt][1];
                        fb[nl * 132 + r + 8]       = acc[mt][nt][2];
                        fb[(nl + 1) * 132 + r + 8] = acc[mt][nt][3];
                    }
            }
            __syncthreads();
            #pragma unroll
            for (int j = 0; j < 16; j++) {
                int nrow = (tid >> 5) * 16 + j;
                int n = n0 + nh * 128 + nrow;
                int r = lane * 4;
                float4 d = *reinterpret_cast<const float4*>(fb + nrow * 132 + r);
                __nv_bfloat16 h0, l0, h1, l1, h2, l2, h3, l3;
                split2(d.x + g_bcat[r + 0], h0, l0);
                split2(d.y + g_bcat[r + 1], h1, l1);
                split2(d.z + g_bcat[r + 2], h2, l2);
                split2(d.w + g_bcat[r + 3], h3, l3);
                uint2 hp = make_uint2(packbf(h0, h1), packbf(h2, h3));
                uint2 lp = make_uint2(packbf(l0, l1), packbf(l2, l3));
                size_t o;
                __nv_bfloat16 *dh, *dl;
                if (r < 64) { o = ((size_t)b * NN + n) * CQ + r;      dh = g_qTh; dl = g_qTl; }
                else        { o = ((size_t)b * NN + n) * CQ + r - 64; dh = g_kTh; dl = g_kTl; }
                *reinterpret_cast<uint2*>(dh + o) = hp;
                *reinterpret_cast<uint2*>(dl + o) = lp;
            }
        }
    } else {
        int c0 = r0 - 128;
        for (int h = 0; h < 2; h++) {
            __syncthreads();
            stage_rows(fb, h, acc, wm, wn, lane);
            __syncthreads();
            #pragma unroll
            for (int j = 0; j < 8; j++) {
                int row = (tid >> 5) * 8 + j;
                int c = c0 + h * 64 + row;
                float bias = g_bcat[r0 + h * 64 + row];
                #pragma unroll
                for (int cg = 0; cg < 2; cg++) {
                    int col = cg * 128 + lane * 4;
                    float4 d = *reinterpret_cast<const float4*>(fb + row * 264 + col);
                    __nv_bfloat16 h0, l0, h1, l1, h2, l2, h3, l3;
                    split2(d.x + bias, h0, l0);
                    split2(d.y + bias, h1, l1);
                    split2(d.z + bias, h2, l2);
                    split2(d.w + bias, h3, l3);
                    size_t o = ((size_t)b * CC + c) * NN + n0 + col;
                    *reinterpret_cast<uint2*>(g_vh + o) = make_uint2(packbf(h0, h1), packbf(h2, h3));
                    *reinterpret_cast<uint2*>(g_vl + o) = make_uint2(packbf(l0, l1), packbf(l2, l3));
                }
            }
        }
    }
}

// =================================================================
// QK: D[m][n] = kT[m]·qT[n]; pT = bf16(exp(D)); csum += rounded row sums
// =================================================================
__global__ __launch_bounds__(256, 1)
void gemm_qk_mma(void) {
    extern __shared__ __align__(16) char sm[];
    uint32_t su = smem_u32(sm);
    int b = blockIdx.z, m0 = blockIdx.y * 128, n0 = blockIdx.x * 256;
    const __nv_bfloat16* Ah = g_kTh + ((size_t)b * NN + m0) * CQ;
    const __nv_bfloat16* Al = g_kTl + ((size_t)b * NN + m0) * CQ;
    const __nv_bfloat16* Bh = g_qTh + ((size_t)b * NN + n0) * CQ;
    const __nv_bfloat16* Bl = g_qTl + ((size_t)b * NN + n0) * CQ;
    float acc[4][8][4];
    run_gemm<true>(su, Ah, Al, CQ, Bh, Bl, CQ, CQ / 32, acc);

    int tid = threadIdx.x, lane = tid & 31, wid = tid >> 5;
    int wm = wid >> 2, wn = wid & 3;
    float* fb = (float*)sm;
    for (int h = 0; h < 2; h++) {
        __syncthreads();
        stage_rows(fb, h, acc, wm, wn, lane);
        __syncthreads();
        #pragma unroll
        for (int j = 0; j < 8; j++) {
            int row = (tid >> 5) * 8 + j;
            int m = m0 + h * 64 + row;
            float rs = 0.f;
            #pragma unroll
            for (int cg = 0; cg < 2; cg++) {
                int col = cg * 128 + lane * 4;
                float4 d = *reinterpret_cast<const float4*>(fb + row * 264 + col);
                __nv_bfloat16 e0 = __float2bfloat16(__expf(d.x));
                __nv_bfloat16 e1 = __float2bfloat16(__expf(d.y));
                __nv_bfloat16 e2 = __float2bfloat16(__expf(d.z));
                __nv_bfloat16 e3 = __float2bfloat16(__expf(d.w));
                rs += __bfloat162float(e0) + __bfloat162float(e1)
                    + __bfloat162float(e2) + __bfloat162float(e3);
                size_t o = ((size_t)b * NN + m) * NN + n0 + col;
                *reinterpret_cast<uint2*>(g_pTh + o) = make_uint2(packbf(e0, e1), packbf(e2, e3));
            }
            #pragma unroll
            for (int of = 16; of; of >>= 1) rs += __shfl_xor_sync(0xffffffffu, rs, of);
            if (lane == 0) atomicAdd(&g_csum[b * NN + m], rs);
        }
    }
}

// =================================================================
// invert csum -> cinv
// =================================================================
__global__ void inv_k(void) {
    int i = blockIdx.x * blockDim.x + threadIdx.x;
    if (i < BB * NN) g_cinv[i] = 1.0f / g_csum[i];
}

// =================================================================
// AV (2-pass, B = p hi only): D[c][m] = v[c]·pT[m]; out = gamma*cinv*D + x
// =================================================================
__global__ __launch_bounds__(256, 1)
void gemm_av_mma(const float* __restrict__ x, const float* __restrict__ gamma,
                 float* __restrict__ out) {
    extern __shared__ __align__(16) char sm[];
    uint32_t su = smem_u32(sm);
    int b = blockIdx.z, m0 = blockIdx.x * 256, c0 = blockIdx.y * 128;
    const __nv_bfloat16* Ah = g_vh  + ((size_t)b * CC + c0) * NN;
    const __nv_bfloat16* Al = g_vl  + ((size_t)b * CC + c0) * NN;
    const __nv_bfloat16* Bh = g_pTh + ((size_t)b * NN + m0) * NN;
    float acc[4][8][4];
    run_gemm<false>(su, Ah, Al, NN, Bh, (const __nv_bfloat16*)0, NN, NN / 32, acc);

    int tid = threadIdx.x, lane = tid & 31, wid = tid >> 5;
    int wm = wid >> 2, wn = wid & 3;
    float* fb = (float*)sm;
    float gm = *gamma;
    for (int h = 0; h < 2; h++) {
        __syncthreads();
        stage_rows(fb, h, acc, wm, wn, lane);
        __syncthreads();
        #pragma unroll
        for (int j = 0; j < 8; j++) {
            int row = (tid >> 5) * 8 + j;
            int c = c0 + h * 64 + row;
            #pragma unroll
            for (int cg = 0; cg < 2; cg++) {
                int col = cg * 128 + lane * 4;
                int m = m0 + col;
                float4 d  = *reinterpret_cast<const float4*>(fb + row * 264 + col);
                float4 ci = *reinterpret_cast<const float4*>(g_cinv + b * NN + m);
                size_t o = ((size_t)b * CC + c) * NN + m;
                float4 xv = *reinterpret_cast<const float4*>(x + o);
                float4 ov;
                ov.x = gm * ci.x * d.x + xv.x;
                ov.y = gm * ci.y * d.y + xv.y;
                ov.z = gm * ci.z * d.z + xv.z;
                ov.w = gm * ci.w * d.w + xv.w;
                *reinterpret_cast<float4*>(out + o) = ov;
            }
        }
    }
}

// =================================================================
extern "C" void kernel_launch(void* const* d_in, const int* in_sizes, int n_in,
                              void* d_out, int out_size) {
    const float* x     = (const float*)d_in[0];
    const float* Wq    = (const float*)d_in[1];
    const float* bq    = (const float*)d_in[2];
    const float* uq    = (const float*)d_in[3];
    const float* Wk    = (const float*)d_in[4];
    const float* bk    = (const float*)d_in[5];
    const float* uk    = (const float*)d_in[6];
    const float* Wv    = (const float*)d_in[7];
    const float* bv    = (const float*)d_in[8];
    const float* uv    = (const float*)d_in[9];
    const float* gamma = (const float*)d_in[10];
    float* out = (float*)d_out;

    static int inited = 0;
    if (!inited) {
        cudaFuncSetAttribute(proj_mma,    cudaFuncAttributeMaxDynamicSharedMemorySize, SMEM_P3);
        cudaFuncSetAttribute(gemm_qk_mma, cudaFuncAttributeMaxDynamicSharedMemorySize, SMEM_P3);
        cudaFuncSetAttribute(gemm_av_mma, cudaFuncAttributeMaxDynamicSharedMemorySize, SMEM_P2);
        inited = 1;
    }

    spectral_k<<<3, 512>>>(Wq, uq, Wk, uk, Wv, uv);
    build_w2k<<<(MR * CC + 255) / 256, 256>>>(Wq, bq, Wk, bk, Wv, bv);
    xsplit_k<<<dim3(NN / 32, CC / 32, BB), dim3(32, 8)>>>(x);
    proj_mma<<<dim3(NN / 256, MR / 128, BB), 256, SMEM_P3>>>();
    gemm_qk_mma<<<dim3(NN / 256, NN / 128, BB), 256, SMEM_P3>>>();
    inv_k<<<(BB * NN + 255) / 256, 256>>>();
    gemm_av_mma<<<dim3(NN / 256, CC / 128, BB), 256, SMEM_P2>>>(x, gamma, out);
}

// round 11
// speedup vs baseline: 1.3872x; 1.3872x over previous
#include <cuda_runtime.h>
#include <cuda_bf16.h>
#include <cstdint>

#define BB 32
#define CC 512
#define NN 1024
#define CQ 64
#define MR 640

// ---------------- scratch (device globals; no cudaMalloc) ----------------
__device__ float g_scale[3];
__device__ float g_bcat[MR];
__device__ __align__(16) __nv_bfloat16 g_w2h[MR * CC];
__device__ __align__(16) __nv_bfloat16 g_w2l[MR * CC];
__device__ __align__(16) __nv_bfloat16 g_xTh[(size_t)BB * NN * CC];
__device__ __align__(16) __nv_bfloat16 g_xTl[(size_t)BB * NN * CC];
__device__ __align__(16) __nv_bfloat16 g_qTh[(size_t)BB * NN * CQ];
__device__ __align__(16) __nv_bfloat16 g_qTl[(size_t)BB * NN * CQ];
__device__ __align__(16) __nv_bfloat16 g_kTh[(size_t)BB * NN * CQ];
__device__ __align__(16) __nv_bfloat16 g_kTl[(size_t)BB * NN * CQ];
__device__ __align__(16) __nv_bfloat16 g_vh [(size_t)BB * CC * NN];
__device__ __align__(16) __nv_bfloat16 g_pTh[(size_t)BB * NN * NN];
__device__ float g_csum[BB * NN];
__device__ float g_cinv[BB * NN];

// ---------------- helpers ----------------
__device__ __forceinline__ uint32_t smem_u32(const void* p) {
    uint32_t a;
    asm("{ .reg .u64 t; cvta.to.shared.u64 t, %1; cvt.u32.u64 %0, t; }" : "=r"(a) : "l"(p));
    return a;
}
__device__ __forceinline__ void cp16(uint32_t s, const void* g) {
    asm volatile("cp.async.cg.shared.global [%0], [%1], 16;" :: "r"(s), "l"(g));
}
__device__ __forceinline__ void cp_commit() { asm volatile("cp.async.commit_group;" ::: "memory"); }
__device__ __forceinline__ void cp_wait1()  { asm volatile("cp.async.wait_group 1;" ::: "memory"); }
__device__ __forceinline__ void cp_wait0()  { asm volatile("cp.async.wait_group 0;" ::: "memory"); }

__device__ __forceinline__ void ldsm4(uint32_t r[4], uint32_t addr) {
    asm volatile("ldmatrix.sync.aligned.m8n8.x4.shared.b16 {%0,%1,%2,%3}, [%4];"
        : "=r"(r[0]), "=r"(r[1]), "=r"(r[2]), "=r"(r[3]) : "r"(addr));
}

__device__ __forceinline__ void mma16816(float* c, const uint32_t a[4], uint32_t b0, uint32_t b1) {
    asm volatile(
        "mma.sync.aligned.m16n8k16.row.col.f32.bf16.bf16.f32 "
        "{%0,%1,%2,%3}, {%4,%5,%6,%7}, {%8,%9}, {%0,%1,%2,%3};"
        : "+f"(c[0]), "+f"(c[1]), "+f"(c[2]), "+f"(c[3])
        : "r"(a[0]), "r"(a[1]), "r"(a[2]), "r"(a[3]), "r"(b0), "r"(b1));
}

__device__ __forceinline__ void split2(float f, __nv_bfloat16& h, __nv_bfloat16& l) {
    h = __float2bfloat16(f);
    l = __float2bfloat16(f - __bfloat162float(h));
}
__device__ __forceinline__ uint32_t packbf(__nv_bfloat16 a, __nv_bfloat16 b) {
    __nv_bfloat162 t(a, b);
    return *reinterpret_cast<uint32_t*>(&t);
}

// ---------------- GEMM core: CTA tile 128x128, K-chunk 32, pass count P ----
// P=3: (Ah+Al)*Bh + Ah*Bl   (full hi/lo, err ~2^-16)
// P=2: (Ah+Al)*Bh           (err ~2^-9, OK when output is rounded to bf16)
// P=1:  Ah*Bh               (exact product of stored bf16 values)
// smem per stage: Ah[, Al], Bh[, Bl], each 128 rows x 32 bf16 at stride 80B
// (conflict-free LDSM: banks r*20%32 distinct per 8 rows).
#define ARR_B   10240u
#define SMEM_S3 (2u * 4u * ARR_B)   // 81920
#define SMEM_S2 (2u * 3u * ARR_B)   // 61440
#define SMEM_S1 (2u * 2u * ARR_B)   // 40960

template<int P>
__device__ __forceinline__ void issue_chunk(uint32_t su, int stage,
        const __nv_bfloat16* Ah, const __nv_bfloat16* Al, int lda,
        const __nv_bfloat16* Bh, const __nv_bfloat16* Bl, int ldb,
        int koff, int tid) {
    const uint32_t STG  = (P == 3 ? 4u : (P == 2 ? 3u : 2u)) * ARR_B;
    const uint32_t OFFB = (P >= 2 ? 2u : 1u) * ARR_B;
    uint32_t sb = su + (uint32_t)stage * STG;
    int row = tid >> 2, seg = tid & 3;
    uint32_t so = (uint32_t)(row * 80 + seg * 16);
    uint32_t so2 = (uint32_t)((row + 64) * 80 + seg * 16);
    size_t go  = (size_t)row * lda + koff + seg * 8;
    size_t go2 = (size_t)(row + 64) * lda + koff + seg * 8;
    cp16(sb + so,  Ah + go);
    cp16(sb + so2, Ah + go2);
    if (P >= 2) {
        cp16(sb + ARR_B + so,  Al + go);
        cp16(sb + ARR_B + so2, Al + go2);
    }
    size_t gb  = (size_t)row * ldb + koff + seg * 8;
    size_t gb2 = (size_t)(row + 64) * ldb + koff + seg * 8;
    cp16(sb + OFFB + so,  Bh + gb);
    cp16(sb + OFFB + so2, Bh + gb2);
    if (P == 3) {
        cp16(sb + OFFB + ARR_B + so,  Bl + gb);
        cp16(sb + OFFB + ARR_B + so2, Bl + gb2);
    }
    cp_commit();
}

template<int P>
__device__ __forceinline__ void compute_chunk(uint32_t su, int stage,
        int wm, int wn, int lane, float acc[4][4][4]) {
    const uint32_t STG  = (P == 3 ? 4u : (P == 2 ? 3u : 2u)) * ARR_B;
    const uint32_t OFFB = (P >= 2 ? 2u : 1u) * ARR_B;
    uint32_t sb = su + (uint32_t)stage * STG;
    int j = lane >> 3, r7 = lane & 7;
    uint32_t Ab = sb + (uint32_t)((wm * 64 + (j & 1) * 8 + r7) * 80 + (j >> 1) * 16);
    uint32_t Bb = sb + OFFB + (uint32_t)((wn * 32 + (j >> 1) * 8 + r7) * 80 + (j & 1) * 16);
    #pragma unroll
    for (int kk = 0; kk < 2; kk++) {
        uint32_t ko = (uint32_t)(kk * 32);
        uint32_t ah[4][4], al[4][4], bh[2][4], bl[2][4];
        #pragma unroll
        for (int mt = 0; mt < 4; mt++) ldsm4(ah[mt], Ab + (uint32_t)(mt * 1280) + ko);
        if (P >= 2) {
            #pragma unroll
            for (int mt = 0; mt < 4; mt++) ldsm4(al[mt], Ab + ARR_B + (uint32_t)(mt * 1280) + ko);
        }
        #pragma unroll
        for (int np = 0; np < 2; np++) ldsm4(bh[np], Bb + (uint32_t)(np * 1280) + ko);
        if (P == 3) {
            #pragma unroll
            for (int np = 0; np < 2; np++) ldsm4(bl[np], Bb + ARR_B + (uint32_t)(np * 1280) + ko);
        }
        #pragma unroll
        for (int mt = 0; mt < 4; mt++)
            #pragma unroll
            for (int nt = 0; nt < 4; nt++) {
                int np = nt >> 1, o = (nt & 1) * 2;
                float* C = acc[mt][nt];
                mma16816(C, ah[mt], bh[np][o], bh[np][o + 1]);
                if (P >= 2) mma16816(C, al[mt], bh[np][o], bh[np][o + 1]);
                if (P == 3) mma16816(C, ah[mt], bl[np][o], bl[np][o + 1]);
            }
    }
}

template<int P>
__device__ __forceinline__ void run_gemm(uint32_t su,
        const __nv_bfloat16* Ah, const __nv_bfloat16* Al, int lda,
        const __nv_bfloat16* Bh, const __nv_bfloat16* Bl, int ldb,
        int nch, float acc[4][4][4]) {
    int tid = threadIdx.x, lane = tid & 31, wid = tid >> 5;
    int wm = wid >> 2, wn = wid & 3;
    #pragma unroll
    for (int i = 0; i < 4; i++)
        #pragma unroll
        for (int j = 0; j < 4; j++)
            #pragma unroll
            for (int e = 0; e < 4; e++) acc[i][j][e] = 0.f;

    issue_chunk<P>(su, 0, Ah, Al, lda, Bh, Bl, ldb, 0, tid);
    issue_chunk<P>(su, 1, Ah, Al, lda, Bh, Bl, ldb, 32, tid);
    for (int ch = 0; ch < nch; ch++) {
        if (ch == nch - 1) cp_wait0(); else cp_wait1();
        __syncthreads();
        compute_chunk<P>(su, ch & 1, wm, wn, lane, acc);
        __syncthreads();
        if (ch + 2 < nch)
            issue_chunk<P>(su, ch & 1, Ah, Al, lda, Bh, Bl, ldb, (ch + 2) * 32, tid);
    }
}

// Stage one 64-row half of the 128x128 fp32 result into smem (stride 132).
__device__ __forceinline__ void stage_half(float* fb, int h, float acc[4][4][4]) {
    int tid = threadIdx.x, lane = tid & 31, wid = tid >> 5;
    int wm = wid >> 2, wn = wid & 3;
    if (wm != h) return;
    int g = lane >> 2, t = lane & 3;
    #pragma unroll
    for (int mt = 0; mt < 4; mt++)
        #pragma unroll
        for (int nt = 0; nt < 4; nt++) {
            float* p = fb + (mt * 16 + g) * 132 + wn * 32 + nt * 8 + 2 * t;
            p[0] = acc[mt][nt][0]; p[1] = acc[mt][nt][1];
            p[8 * 132] = acc[mt][nt][2]; p[8 * 132 + 1] = acc[mt][nt][3];
        }
}

// =================================================================
// Spectral norm (fp32)
// =================================================================
__global__ void spectral_k(const float* __restrict__ Wq, const float* __restrict__ uq,
                           const float* __restrict__ Wk, const float* __restrict__ uk,
                           const float* __restrict__ Wv, const float* __restrict__ uv) {
    const float* W; const float* u; int out;
    if (blockIdx.x == 0)      { W = Wq; u = uq; out = CQ; }
    else if (blockIdx.x == 1) { W = Wk; u = uk; out = CQ; }
    else                      { W = Wv; u = uv; out = CC; }
    const int in = CC;
    __shared__ float sv[CC];
    __shared__ float st[CC];
    __shared__ float red[16];
    int tid = threadIdx.x, lane = tid & 31, w = tid >> 5;

    float acc = 0.f;
    for (int i = 0; i < out; i++) acc += W[i * in + tid] * u[i];
    sv[tid] = acc;

    float s = acc * acc;
    #pragma unroll
    for (int o = 16; o; o >>= 1) s += __shfl_xor_sync(0xffffffffu, s, o);
    if (lane == 0) red[w] = s;
    __syncthreads();
    if (tid < 16) {
        float r = red[tid];
        #pragma unroll
        for (int o = 8; o; o >>= 1) r += __shfl_xor_sync(0xffffu, r, o);
        if (tid == 0) red[0] = r;
    }
    __syncthreads();
    float inv = rsqrtf(red[0]);
    __syncthreads();

    for (int i = w; i < out; i += 16) {
        float a = 0.f;
        for (int jj = lane; jj < in; jj += 32) a += W[i * in + jj] * sv[jj];
        #pragma unroll
        for (int o = 16; o; o >>= 1) a += __shfl_xor_sync(0xffffffffu, a, o);
        if (lane == 0) st[i] = a * inv;
    }
    __syncthreads();

    float q = (tid < out) ? st[tid] * st[tid] : 0.f;
    #pragma unroll
    for (int o = 16; o; o >>= 1) q += __shfl_xor_sync(0xffffffffu, q, o);
    if (lane == 0) red[w] = q;
    __syncthreads();
    if (tid == 0) {
        float r = 0.f;
        #pragma unroll
        for (int i = 0; i < 16; i++) r += red[i];
        g_scale[blockIdx.x] = rsqrtf(r);
    }
}

// =================================================================
// Scaled concatenated weights -> bf16 hi/lo + fp32 bias; also zero csum
// =================================================================
__global__ void build_w2k(const float* __restrict__ Wq, const float* __restrict__ bq,
                          const float* __restrict__ Wk, const float* __restrict__ bk,
                          const float* __restrict__ Wv, const float* __restrict__ bv) {
    int idx = blockIdx.x * blockDim.x + threadIdx.x;
    if (idx >= MR * CC) return;
    if (idx < BB * NN) g_csum[idx] = 0.f;
    int r = idx >> 9, c = idx & (CC - 1);
    float wv, sc;
    if (r < CQ)          { wv = Wq[r * CC + c];            sc = g_scale[0]; }
    else if (r < 2 * CQ) { wv = Wk[(r - CQ) * CC + c];     sc = g_scale[1]; }
    else                 { wv = Wv[(r - 2 * CQ) * CC + c]; sc = g_scale[2]; }
    __nv_bfloat16 h, l;
    split2(wv * sc, h, l);
    g_w2h[idx] = h; g_w2l[idx] = l;
    if (c == 0)
        g_bcat[r] = (r < CQ) ? bq[r] : (r < 2 * CQ ? bk[r - CQ] : bv[r - 2 * CQ]);
}

// =================================================================
// Transpose+split x: [b][c][n] fp32 -> xT hi/lo bf16 [b][n][c]
// =================================================================
__global__ void xsplit_k(const float* __restrict__ x) {
    __shared__ float t[32][33];
    int b = blockIdx.z, n0 = blockIdx.x * 32, c0 = blockIdx.y * 32;
    int tx = threadIdx.x, ty = threadIdx.y;   // 32 x 8
    const float* xb = x + (size_t)b * CC * NN;
    #pragma unroll
    for (int j = 0; j < 4; j++)
        t[ty + 8 * j][tx] = xb[(size_t)(c0 + ty + 8 * j) * NN + n0 + tx];
    __syncthreads();
    #pragma unroll
    for (int j = 0; j < 4; j++) {
        int n = n0 + ty + 8 * j;
        __nv_bfloat16 h, l;
        split2(t[tx][ty + 8 * j], h, l);
        size_t o = ((size_t)b * NN + n) * CC + c0 + tx;
        g_xTh[o] = h; g_xTl[o] = l;
    }
}

// =================================================================
// proj_qk (3-pass): D[n][r] = xT[n]·w[r] + b[r] -> qT/kT hi/lo [b][n][64]
// =================================================================
__global__ __launch_bounds__(256, 2)
void proj_qk_mma(void) {
    extern __shared__ __align__(16) char sm[];
    uint32_t su = smem_u32(sm);
    int b = blockIdx.z, n0 = blockIdx.x * 128;
    const __nv_bfloat16* Ah = g_xTh + ((size_t)b * NN + n0) * CC;
    const __nv_bfloat16* Al = g_xTl + ((size_t)b * NN + n0) * CC;
    float acc[4][4][4];
    run_gemm<3>(su, Ah, Al, CC, g_w2h, g_w2l, CC, CC / 32, acc);

    float* fb = (float*)sm;
    int tid = threadIdx.x, lane = tid & 31;
    for (int h = 0; h < 2; h++) {
        __syncthreads();
        stage_half(fb, h, acc);
        __syncthreads();
        #pragma unroll
        for (int j = 0; j < 8; j++) {
            int r = (tid >> 5) + j * 8;
            int n = n0 + h * 64 + r;
            int rr = lane * 4;
            const float* p = fb + r * 132 + rr;
            uint32_t hp[2], lp[2];
            #pragma unroll
            for (int e = 0; e < 2; e++) {
                float f0 = p[2 * e]     + g_bcat[rr + 2 * e];
                float f1 = p[2 * e + 1] + g_bcat[rr + 2 * e + 1];
                __nv_bfloat16 h0, l0, h1, l1;
                split2(f0, h0, l0); split2(f1, h1, l1);
                hp[e] = packbf(h0, h1); lp[e] = packbf(l0, l1);
            }
            size_t o;
            __nv_bfloat16 *dh, *dl;
            if (rr < 64) { o = ((size_t)b * NN + n) * CQ + rr;      dh = g_qTh; dl = g_qTl; }
            else         { o = ((size_t)b * NN + n) * CQ + rr - 64; dh = g_kTh; dl = g_kTl; }
            *reinterpret_cast<uint2*>(dh + o) = *reinterpret_cast<uint2*>(hp);
            *reinterpret_cast<uint2*>(dl + o) = *reinterpret_cast<uint2*>(lp);
        }
    }
}

// =================================================================
// proj_v (2-pass): D[c][n] = (wh+wl)[c]·xh[n] + bv[c] -> v bf16 [b][c][n]
// =================================================================
__global__ __launch_bounds__(256, 2)
void proj_v_mma(void) {
    extern __shared__ __align__(16) char sm[];
    uint32_t su = smem_u32(sm);
    int b = blockIdx.z, n0 = blockIdx.x * 128, c0 = blockIdx.y * 128;
    const __nv_bfloat16* Ah = g_w2h + (size_t)(2 * CQ + c0) * CC;
    const __nv_bfloat16* Al = g_w2l + (size_t)(2 * CQ + c0) * CC;
    const __nv_bfloat16* Bh = g_xTh + ((size_t)b * NN + n0) * CC;
    float acc[4][4][4];
    run_gemm<2>(su, Ah, Al, CC, Bh, (const __nv_bfloat16*)0, CC, CC / 32, acc);

    float* fb = (float*)sm;
    int tid = threadIdx.x, lane = tid & 31;
    for (int h = 0; h < 2; h++) {
        __syncthreads();
        stage_half(fb, h, acc);
        __syncthreads();
        #pragma unroll
        for (int j = 0; j < 8; j++) {
            int r = (tid >> 5) + j * 8;
            int c = c0 + h * 64 + r;
            float bias = g_bcat[2 * CQ + c];
            const float* p = fb + r * 132 + lane * 4;
            uint32_t hp[2];
            #pragma unroll
            for (int e = 0; e < 2; e++) {
                __nv_bfloat16 h0 = __float2bfloat16(p[2 * e] + bias);
                __nv_bfloat16 h1 = __float2bfloat16(p[2 * e + 1] + bias);
                hp[e] = packbf(h0, h1);
            }
            size_t o = ((size_t)b * CC + c) * NN + n0 + lane * 4;
            *reinterpret_cast<uint2*>(g_vh + o) = *reinterpret_cast<uint2*>(hp);
        }
    }
}

// =================================================================
// QK (3-pass): D[m][n] = kT[m]·qT[n]; pT = bf16(exp(D)); csum += rounded sums
// =================================================================
__global__ __launch_bounds__(256, 2)
void gemm_qk_mma(void) {
    extern __shared__ __align__(16) char sm[];
    uint32_t su = smem_u32(sm);
    int b = blockIdx.z, m0 = blockIdx.y * 128, n0 = blockIdx.x * 128;
    const __nv_bfloat16* Ah = g_kTh + ((size_t)b * NN + m0) * CQ;
    const __nv_bfloat16* Al = g_kTl + ((size_t)b * NN + m0) * CQ;
    const __nv_bfloat16* Bh = g_qTh + ((size_t)b * NN + n0) * CQ;
    const __nv_bfloat16* Bl = g_qTl + ((size_t)b * NN + n0) * CQ;
    float acc[4][4][4];
    run_gemm<3>(su, Ah, Al, CQ, Bh, Bl, CQ, CQ / 32, acc);

    float* fb = (float*)sm;
    int tid = threadIdx.x, lane = tid & 31;
    for (int h = 0; h < 2; h++) {
        __syncthreads();
        stage_half(fb, h, acc);
        __syncthreads();
        #pragma unroll
        for (int j = 0; j < 8; j++) {
            int r = (tid >> 5) + j * 8;       // whole warp shares row r
            int m = m0 + h * 64 + r;
            const float* p = fb + r * 132 + lane * 4;
            uint32_t hp[2];
            float rs = 0.f;
            #pragma unroll
            for (int e = 0; e < 2; e++) {
                __nv_bfloat16 h0 = __float2bfloat16(__expf(p[2 * e]));
                __nv_bfloat16 h1 = __float2bfloat16(__expf(p[2 * e + 1]));
                rs += __bfloat162float(h0) + __bfloat162float(h1);
                hp[e] = packbf(h0, h1);
            }
            size_t o = ((size_t)b * NN + m) * NN + n0 + lane * 4;
            *reinterpret_cast<uint2*>(g_pTh + o) = *reinterpret_cast<uint2*>(hp);
            #pragma unroll
            for (int of = 16; of; of >>= 1) rs += __shfl_xor_sync(0xffffffffu, rs, of);
            if (lane == 0) atomicAdd(&g_csum[b * NN + m], rs);
        }
    }
}

// =================================================================
// invert csum -> cinv
// =================================================================
__global__ void inv_k(void) {
    int i = blockIdx.x * blockDim.x + threadIdx.x;
    if (i < BB * NN) g_cinv[i] = 1.0f / g_csum[i];
}

// =================================================================
// AV (1-pass, exact on stored values): D[c][m] = v[c]·pT[m]
// out = gamma*cinv[m]*D + x
// =================================================================
__global__ __launch_bounds__(256, 2)
void gemm_av_mma(const float* __restrict__ x, const float* __restrict__ gamma,
                 float* __restrict__ out) {
    extern __shared__ __align__(16) char sm[];
    uint32_t su = smem_u32(sm);
    int b = blockIdx.z, m0 = blockIdx.x * 128, c0 = blockIdx.y * 128;
    const __nv_bfloat16* Ah = g_vh  + ((size_t)b * CC + c0) * NN;
    const __nv_bfloat16* Bh = g_pTh + ((size_t)b * NN + m0) * NN;
    float acc[4][4][4];
    run_gemm<1>(su, Ah, (const __nv_bfloat16*)0, NN, Bh, (const __nv_bfloat16*)0, NN, NN / 32, acc);

    float* fb = (float*)sm;
    int tid = threadIdx.x, lane = tid & 31;
    float gm = *gamma;
    for (int h = 0; h < 2; h++) {
        __syncthreads();
        stage_half(fb, h, acc);
        __syncthreads();
        #pragma unroll
        for (int j = 0; j < 8; j++) {
            int r = (tid >> 5) + j * 8;
            int c = c0 + h * 64 + r;
            int m = m0 + lane * 4;
            float4 d = *reinterpret_cast<const float4*>(fb + r * 132 + lane * 4);
            float4 ci = *reinterpret_cast<const float4*>(g_cinv + b * NN + m);
            size_t o = ((size_t)b * CC + c) * NN + m;
            float4 xv = *reinterpret_cast<const float4*>(x + o);
            float4 ov;
            ov.x = gm * ci.x * d.x + xv.x;
            ov.y = gm * ci.y * d.y + xv.y;
            ov.z = gm * ci.z * d.z + xv.z;
            ov.w = gm * ci.w * d.w + xv.w;
            *reinterpret_cast<float4*>(out + o) = ov;
        }
    }
}

// =================================================================
extern "C" void kernel_launch(void* const* d_in, const int* in_sizes, int n_in,
                              void* d_out, int out_size) {
    const float* x     = (const float*)d_in[0];
    const float* Wq    = (const float*)d_in[1];
    const float* bq    = (const float*)d_in[2];
    const float* uq    = (const float*)d_in[3];
    const float* Wk    = (const float*)d_in[4];
    const float* bk    = (const float*)d_in[5];
    const float* uk    = (const float*)d_in[6];
    const float* Wv    = (const float*)d_in[7];
    const float* bv    = (const float*)d_in[8];
    const float* uv    = (const float*)d_in[9];
    const float* gamma = (const float*)d_in[10];
    float* out = (float*)d_out;

    static int inited = 0;
    if (!inited) {
        cudaFuncSetAttribute(proj_qk_mma, cudaFuncAttributeMaxDynamicSharedMemorySize, SMEM_S3);
        cudaFuncSetAttribute(proj_v_mma,  cudaFuncAttributeMaxDynamicSharedMemorySize, SMEM_S2);
        cudaFuncSetAttribute(gemm_qk_mma, cudaFuncAttributeMaxDynamicSharedMemorySize, SMEM_S3);
        cudaFuncSetAttribute(gemm_av_mma, cudaFuncAttributeMaxDynamicSharedMemorySize, SMEM_S1);
        inited = 1;
    }

    spectral_k<<<3, 512>>>(Wq, uq, Wk, uk, Wv, uv);
    build_w2k<<<(MR * CC + 255) / 256, 256>>>(Wq, bq, Wk, bk, Wv, bv);
    xsplit_k<<<dim3(NN / 32, CC / 32, BB), dim3(32, 8)>>>(x);
    proj_qk_mma<<<dim3(NN / 128, 1, BB), 256, SMEM_S3>>>();
    proj_v_mma<<<dim3(NN / 128, CC / 128, BB), 256, SMEM_S2>>>();
    gemm_qk_mma<<<dim3(NN / 128, NN / 128, BB), 256, SMEM_S3>>>();
    inv_k<<<(BB * NN + 255) / 256, 256>>>();
    gemm_av_mma<<<dim3(NN / 128, CC / 128, BB), 256, SMEM_S1>>>(x, gamma, out);
}

// round 12
// speedup vs baseline: 1.4007x; 1.0097x over previous
#include <cuda_runtime.h>
#include <cuda_bf16.h>
#include <cstdint>

#define BB 32
#define CC 512
#define NN 1024
#define CQ 64
#define MR 640

// ---------------- scratch (device globals; no cudaMalloc) ----------------
__device__ float g_scale[3];
__device__ float g_bcat[MR];
__device__ __align__(16) __nv_bfloat16 g_w2h[MR * CC];
__device__ __align__(16) __nv_bfloat16 g_w2l[MR * CC];
__device__ __align__(16) __nv_bfloat16 g_xTh[(size_t)BB * NN * CC];
__device__ __align__(16) __nv_bfloat16 g_xTl[(size_t)BB * NN * CC];
__device__ __align__(16) __nv_bfloat16 g_qTh[(size_t)BB * NN * CQ];
__device__ __align__(16) __nv_bfloat16 g_qTl[(size_t)BB * NN * CQ];
__device__ __align__(16) __nv_bfloat16 g_kTh[(size_t)BB * NN * CQ];
__device__ __align__(16) __nv_bfloat16 g_kTl[(size_t)BB * NN * CQ];
__device__ __align__(16) __nv_bfloat16 g_vh [(size_t)BB * CC * NN];
__device__ __align__(16) __nv_bfloat16 g_pTh[(size_t)BB * NN * NN];
__device__ float g_csum[BB * NN];
__device__ float g_cinv[BB * NN];

// ---------------- helpers ----------------
__device__ __forceinline__ uint32_t smem_u32(const void* p) {
    uint32_t a;
    asm("{ .reg .u64 t; cvta.to.shared.u64 t, %1; cvt.u32.u64 %0, t; }" : "=r"(a) : "l"(p));
    return a;
}
__device__ __forceinline__ void cp16(uint32_t s, const void* g) {
    asm volatile("cp.async.cg.shared.global [%0], [%1], 16;" :: "r"(s), "l"(g));
}
__device__ __forceinline__ void cp_commit() { asm volatile("cp.async.commit_group;" ::: "memory"); }
__device__ __forceinline__ void cp_wait1()  { asm volatile("cp.async.wait_group 1;" ::: "memory"); }
__device__ __forceinline__ void cp_wait0()  { asm volatile("cp.async.wait_group 0;" ::: "memory"); }

__device__ __forceinline__ void ldsm4(uint32_t r[4], uint32_t addr) {
    asm volatile("ldmatrix.sync.aligned.m8n8.x4.shared.b16 {%0,%1,%2,%3}, [%4];"
        : "=r"(r[0]), "=r"(r[1]), "=r"(r[2]), "=r"(r[3]) : "r"(addr));
}

__device__ __forceinline__ void mma16816(float* c, const uint32_t a[4], uint32_t b0, uint32_t b1) {
    asm volatile(
        "mma.sync.aligned.m16n8k16.row.col.f32.bf16.bf16.f32 "
        "{%0,%1,%2,%3}, {%4,%5,%6,%7}, {%8,%9}, {%0,%1,%2,%3};"
        : "+f"(c[0]), "+f"(c[1]), "+f"(c[2]), "+f"(c[3])
        : "r"(a[0]), "r"(a[1]), "r"(a[2]), "r"(a[3]), "r"(b0), "r"(b1));
}

__device__ __forceinline__ void split2(float f, __nv_bfloat16& h, __nv_bfloat16& l) {
    h = __float2bfloat16(f);
    l = __float2bfloat16(f - __bfloat162float(h));
}
__device__ __forceinline__ uint32_t packbf(__nv_bfloat16 a, __nv_bfloat16 b) {
    __nv_bfloat162 t(a, b);
    return *reinterpret_cast<uint32_t*>(&t);
}

// ---------------- GEMM core: CTA tile 128x128, K-chunk 32 ----------------
// P = pass count: 3 = (Ah+Al)*Bh + Ah*Bl ; 2 = (Ah+Al)*Bh ; 1 = Ah*Bh
// S = pipeline stages (2 or 3). smem per stage = (P==3?4:P==2?3:2)*ARR_B.
// Arrays: 128 rows x 32 bf16, stride 80 B -> conflict-free LDSM.
#define ARR_B   10240u
#define SMEM_QKP (2u * 4u * ARR_B)   // 81920: proj_qk / QK (P=3, S=2)
#define SMEM_PV  (3u * 3u * ARR_B)   // 92160: proj_v (P=2, S=3)
#define SMEM_AV  (3u * 2u * ARR_B)   // 61440: AV (P=1, S=3)

template<int P>
__device__ __forceinline__ void issue_chunk(uint32_t su, int stage,
        const __nv_bfloat16* Ah, const __nv_bfloat16* Al, int lda,
        const __nv_bfloat16* Bh, const __nv_bfloat16* Bl, int ldb,
        int koff, int tid) {
    const uint32_t STG  = (P == 3 ? 4u : (P == 2 ? 3u : 2u)) * ARR_B;
    const uint32_t OFFB = (P >= 2 ? 2u : 1u) * ARR_B;
    uint32_t sb = su + (uint32_t)stage * STG;
    int row = tid >> 2, seg = tid & 3;
    uint32_t so  = (uint32_t)(row * 80 + seg * 16);
    uint32_t so2 = (uint32_t)((row + 64) * 80 + seg * 16);
    size_t go  = (size_t)row * lda + koff + seg * 8;
    size_t go2 = (size_t)(row + 64) * lda + koff + seg * 8;
    cp16(sb + so,  Ah + go);
    cp16(sb + so2, Ah + go2);
    if (P >= 2) {
        cp16(sb + ARR_B + so,  Al + go);
        cp16(sb + ARR_B + so2, Al + go2);
    }
    size_t gb  = (size_t)row * ldb + koff + seg * 8;
    size_t gb2 = (size_t)(row + 64) * ldb + koff + seg * 8;
    cp16(sb + OFFB + so,  Bh + gb);
    cp16(sb + OFFB + so2, Bh + gb2);
    if (P == 3) {
        cp16(sb + OFFB + ARR_B + so,  Bl + gb);
        cp16(sb + OFFB + ARR_B + so2, Bl + gb2);
    }
    cp_commit();
}

template<int P>
__device__ __forceinline__ void compute_chunk(uint32_t su, int stage,
        int wm, int wn, int lane, float acc[4][4][4]) {
    const uint32_t STG  = (P == 3 ? 4u : (P == 2 ? 3u : 2u)) * ARR_B;
    const uint32_t OFFB = (P >= 2 ? 2u : 1u) * ARR_B;
    uint32_t sb = su + (uint32_t)stage * STG;
    int j = lane >> 3, r7 = lane & 7;
    uint32_t Ab = sb + (uint32_t)((wm * 64 + (j & 1) * 8 + r7) * 80 + (j >> 1) * 16);
    uint32_t Bb = sb + OFFB + (uint32_t)((wn * 32 + (j >> 1) * 8 + r7) * 80 + (j & 1) * 16);
    #pragma unroll
    for (int kk = 0; kk < 2; kk++) {
        uint32_t ko = (uint32_t)(kk * 32);
        uint32_t ah[4][4], al[4][4], bh[2][4], bl[2][4];
        #pragma unroll
        for (int mt = 0; mt < 4; mt++) ldsm4(ah[mt], Ab + (uint32_t)(mt * 1280) + ko);
        if (P >= 2) {
            #pragma unroll
            for (int mt = 0; mt < 4; mt++) ldsm4(al[mt], Ab + ARR_B + (uint32_t)(mt * 1280) + ko);
        }
        #pragma unroll
        for (int np = 0; np < 2; np++) ldsm4(bh[np], Bb + (uint32_t)(np * 1280) + ko);
        if (P == 3) {
            #pragma unroll
            for (int np = 0; np < 2; np++) ldsm4(bl[np], Bb + ARR_B + (uint32_t)(np * 1280) + ko);
        }
        #pragma unroll
        for (int mt = 0; mt < 4; mt++)
            #pragma unroll
            for (int nt = 0; nt < 4; nt++) {
                int np = nt >> 1, o = (nt & 1) * 2;
                float* C = acc[mt][nt];
                mma16816(C, ah[mt], bh[np][o], bh[np][o + 1]);
                if (P >= 2) mma16816(C, al[mt], bh[np][o], bh[np][o + 1]);
                if (P == 3) mma16816(C, ah[mt], bl[np][o], bl[np][o + 1]);
            }
    }
}

// Single-sync multistage mainloop: wait -> sync -> issue(ch+S-1) -> compute(ch).
// The top-of-iteration barrier proves all warps finished chunk ch-1, so issuing
// into stage (ch+S-1)%S == (ch-1)%S right after it is safe.
template<int P, int S>
__device__ __forceinline__ void run_gemm(uint32_t su,
        const __nv_bfloat16* Ah, const __nv_bfloat16* Al, int lda,
        const __nv_bfloat16* Bh, const __nv_bfloat16* Bl, int ldb,
        int nch, float acc[4][4][4]) {
    int tid = threadIdx.x, lane = tid & 31, wid = tid >> 5;
    int wm = wid >> 2, wn = wid & 3;
    #pragma unroll
    for (int i = 0; i < 4; i++)
        #pragma unroll
        for (int j = 0; j < 4; j++)
            #pragma unroll
            for (int e = 0; e < 4; e++) acc[i][j][e] = 0.f;

    #pragma unroll
    for (int s = 0; s < S - 1; s++)
        issue_chunk<P>(su, s, Ah, Al, lda, Bh, Bl, ldb, s * 32, tid);

    for (int ch = 0; ch < nch; ch++) {
        if (S == 2) { cp_wait0(); }
        else        { if (ch == nch - 1) cp_wait0(); else cp_wait1(); }
        __syncthreads();
        int nx = ch + S - 1;
        if (nx < nch)
            issue_chunk<P>(su, nx % S, Ah, Al, lda, Bh, Bl, ldb, nx * 32, tid);
        compute_chunk<P>(su, ch % S, wm, wn, lane, acc);
    }
    __syncthreads();   // all warps done with operand smem before epilogue reuse
}

// Stage one 64-row half of the 128x128 fp32 result into smem (stride 132).
__device__ __forceinline__ void stage_half(float* fb, int h, float acc[4][4][4]) {
    int tid = threadIdx.x, lane = tid & 31, wid = tid >> 5;
    int wm = wid >> 2, wn = wid & 3;
    if (wm != h) return;
    int g = lane >> 2, t = lane & 3;
    #pragma unroll
    for (int mt = 0; mt < 4; mt++)
        #pragma unroll
        for (int nt = 0; nt < 4; nt++) {
            float* p = fb + (mt * 16 + g) * 132 + wn * 32 + nt * 8 + 2 * t;
            p[0] = acc[mt][nt][0]; p[1] = acc[mt][nt][1];
            p[8 * 132] = acc[mt][nt][2]; p[8 * 132 + 1] = acc[mt][nt][3];
        }
}

// =================================================================
// Spectral norm (fp32)
// =================================================================
__global__ void spectral_k(const float* __restrict__ Wq, const float* __restrict__ uq,
                           const float* __restrict__ Wk, const float* __restrict__ uk,
                           const float* __restrict__ Wv, const float* __restrict__ uv) {
    const float* W; const float* u; int out;
    if (blockIdx.x == 0)      { W = Wq; u = uq; out = CQ; }
    else if (blockIdx.x == 1) { W = Wk; u = uk; out = CQ; }
    else                      { W = Wv; u = uv; out = CC; }
    const int in = CC;
    __shared__ float sv[CC];
    __shared__ float st[CC];
    __shared__ float red[16];
    int tid = threadIdx.x, lane = tid & 31, w = tid >> 5;

    float acc = 0.f;
    for (int i = 0; i < out; i++) acc += W[i * in + tid] * u[i];
    sv[tid] = acc;

    float s = acc * acc;
    #pragma unroll
    for (int o = 16; o; o >>= 1) s += __shfl_xor_sync(0xffffffffu, s, o);
    if (lane == 0) red[w] = s;
    __syncthreads();
    if (tid < 16) {
        float r = red[tid];
        #pragma unroll
        for (int o = 8; o; o >>= 1) r += __shfl_xor_sync(0xffffu, r, o);
        if (tid == 0) red[0] = r;
    }
    __syncthreads();
    float inv = rsqrtf(red[0]);
    __syncthreads();

    for (int i = w; i < out; i += 16) {
        float a = 0.f;
        for (int jj = lane; jj < in; jj += 32) a += W[i * in + jj] * sv[jj];
        #pragma unroll
        for (int o = 16; o; o >>= 1) a += __shfl_xor_sync(0xffffffffu, a, o);
        if (lane == 0) st[i] = a * inv;
    }
    __syncthreads();

    float q = (tid < out) ? st[tid] * st[tid] : 0.f;
    #pragma unroll
    for (int o = 16; o; o >>= 1) q += __shfl_xor_sync(0xffffffffu, q, o);
    if (lane == 0) red[w] = q;
    __syncthreads();
    if (tid == 0) {
        float r = 0.f;
        #pragma unroll
        for (int i = 0; i < 16; i++) r += red[i];
        g_scale[blockIdx.x] = rsqrtf(r);
    }
}

// =================================================================
// Scaled concatenated weights -> bf16 hi/lo + fp32 bias; also zero csum
// =================================================================
__global__ void build_w2k(const float* __restrict__ Wq, const float* __restrict__ bq,
                          const float* __restrict__ Wk, const float* __restrict__ bk,
                          const float* __restrict__ Wv, const float* __restrict__ bv) {
    int idx = blockIdx.x * blockDim.x + threadIdx.x;
    if (idx >= MR * CC) return;
    if (idx < BB * NN) g_csum[idx] = 0.f;
    int r = idx >> 9, c = idx & (CC - 1);
    float wv, sc;
    if (r < CQ)          { wv = Wq[r * CC + c];            sc = g_scale[0]; }
    else if (r < 2 * CQ) { wv = Wk[(r - CQ) * CC + c];     sc = g_scale[1]; }
    else                 { wv = Wv[(r - 2 * CQ) * CC + c]; sc = g_scale[2]; }
    __nv_bfloat16 h, l;
    split2(wv * sc, h, l);
    g_w2h[idx] = h; g_w2l[idx] = l;
    if (c == 0)
        g_bcat[r] = (r < CQ) ? bq[r] : (r < 2 * CQ ? bk[r - CQ] : bv[r - 2 * CQ]);
}

// =================================================================
// Transpose+split x: [b][c][n] fp32 -> xT hi/lo bf16 [b][n][c]
// =================================================================
__global__ void xsplit_k(const float* __restrict__ x) {
    __shared__ float t[32][33];
    int b = blockIdx.z, n0 = blockIdx.x * 32, c0 = blockIdx.y * 32;
    int tx = threadIdx.x, ty = threadIdx.y;   // 32 x 8
    const float* xb = x + (size_t)b * CC * NN;
    #pragma unroll
    for (int j = 0; j < 4; j++)
        t[ty + 8 * j][tx] = xb[(size_t)(c0 + ty + 8 * j) * NN + n0 + tx];
    __syncthreads();
    #pragma unroll
    for (int j = 0; j < 4; j++) {
        int n = n0 + ty + 8 * j;
        __nv_bfloat16 h, l;
        split2(t[tx][ty + 8 * j], h, l);
        size_t o = ((size_t)b * NN + n) * CC + c0 + tx;
        g_xTh[o] = h; g_xTl[o] = l;
    }
}

// =================================================================
// proj_qk (P=3,S=2): D[n][r] = xT[n]·w[r] + b[r] -> qT/kT hi/lo [b][n][64]
// =================================================================
__global__ __launch_bounds__(256, 2)
void proj_qk_mma(void) {
    extern __shared__ __align__(16) char sm[];
    uint32_t su = smem_u32(sm);
    int b = blockIdx.z, n0 = blockIdx.x * 128;
    const __nv_bfloat16* Ah = g_xTh + ((size_t)b * NN + n0) * CC;
    const __nv_bfloat16* Al = g_xTl + ((size_t)b * NN + n0) * CC;
    float acc[4][4][4];
    run_gemm<3, 2>(su, Ah, Al, CC, g_w2h, g_w2l, CC, CC / 32, acc);

    float* fb = (float*)sm;
    int tid = threadIdx.x, lane = tid & 31;
    for (int h = 0; h < 2; h++) {
        __syncthreads();
        stage_half(fb, h, acc);
        __syncthreads();
        #pragma unroll
        for (int j = 0; j < 8; j++) {
            int r = (tid >> 5) + j * 8;
            int n = n0 + h * 64 + r;
            int rr = lane * 4;
            const float* p = fb + r * 132 + rr;
            uint32_t hp[2], lp[2];
            #pragma unroll
            for (int e = 0; e < 2; e++) {
                float f0 = p[2 * e]     + g_bcat[rr + 2 * e];
                float f1 = p[2 * e + 1] + g_bcat[rr + 2 * e + 1];
                __nv_bfloat16 h0, l0, h1, l1;
                split2(f0, h0, l0); split2(f1, h1, l1);
                hp[e] = packbf(h0, h1); lp[e] = packbf(l0, l1);
            }
            size_t o;
            __nv_bfloat16 *dh, *dl;
            if (rr < 64) { o = ((size_t)b * NN + n) * CQ + rr;      dh = g_qTh; dl = g_qTl; }
            else         { o = ((size_t)b * NN + n) * CQ + rr - 64; dh = g_kTh; dl = g_kTl; }
            *reinterpret_cast<uint2*>(dh + o) = *reinterpret_cast<uint2*>(hp);
            *reinterpret_cast<uint2*>(dl + o) = *reinterpret_cast<uint2*>(lp);
        }
    }
}

// =================================================================
// proj_v (P=2,S=3): D[c][n] = (wh+wl)[c]·xh[n] + bv[c] -> v bf16 [b][c][n]
// =================================================================
__global__ __launch_bounds__(256, 2)
void proj_v_mma(void) {
    extern __shared__ __align__(16) char sm[];
    uint32_t su = smem_u32(sm);
    int b = blockIdx.z, n0 = blockIdx.x * 128, c0 = blockIdx.y * 128;
    const __nv_bfloat16* Ah = g_w2h + (size_t)(2 * CQ + c0) * CC;
    const __nv_bfloat16* Al = g_w2l + (size_t)(2 * CQ + c0) * CC;
    const __nv_bfloat16* Bh = g_xTh + ((size_t)b * NN + n0) * CC;
    float acc[4][4][4];
    run_gemm<2, 3>(su, Ah, Al, CC, Bh, (const __nv_bfloat16*)0, CC, CC / 32, acc);

    float* fb = (float*)sm;
    int tid = threadIdx.x, lane = tid & 31;
    for (int h = 0; h < 2; h++) {
        __syncthreads();
        stage_half(fb, h, acc);
        __syncthreads();
        #pragma unroll
        for (int j = 0; j < 8; j++) {
            int r = (tid >> 5) + j * 8;
            int c = c0 + h * 64 + r;
            float bias = g_bcat[2 * CQ + c];
            const float* p = fb + r * 132 + lane * 4;
            uint32_t hp[2];
            #pragma unroll
            for (int e = 0; e < 2; e++) {
                __nv_bfloat16 h0 = __float2bfloat16(p[2 * e] + bias);
                __nv_bfloat16 h1 = __float2bfloat16(p[2 * e + 1] + bias);
                hp[e] = packbf(h0, h1);
            }
            size_t o = ((size_t)b * CC + c) * NN + n0 + lane * 4;
            *reinterpret_cast<uint2*>(g_vh + o) = *reinterpret_cast<uint2*>(hp);
        }
    }
}

// =================================================================
// QK (P=3,S=2): D[m][n] = kT[m]·qT[n]; pT = bf16(exp(D)); csum += rounded sums
// =================================================================
__global__ __launch_bounds__(256, 2)
void gemm_qk_mma(void) {
    extern __shared__ __align__(16) char sm[];
    uint32_t su = smem_u32(sm);
    int b = blockIdx.z, m0 = blockIdx.y * 128, n0 = blockIdx.x * 128;
    const __nv_bfloat16* Ah = g_kTh + ((size_t)b * NN + m0) * CQ;
    const __nv_bfloat16* Al = g_kTl + ((size_t)b * NN + m0) * CQ;
    const __nv_bfloat16* Bh = g_qTh + ((size_t)b * NN + n0) * CQ;
    const __nv_bfloat16* Bl = g_qTl + ((size_t)b * NN + n0) * CQ;
    float acc[4][4][4];
    run_gemm<3, 2>(su, Ah, Al, CQ, Bh, Bl, CQ, CQ / 32, acc);

    float* fb = (float*)sm;
    int tid = threadIdx.x, lane = tid & 31;
    for (int h = 0; h < 2; h++) {
        __syncthreads();
        stage_half(fb, h, acc);
        __syncthreads();
        #pragma unroll
        for (int j = 0; j < 8; j++) {
            int r = (tid >> 5) + j * 8;       // whole warp shares row r
            int m = m0 + h * 64 + r;
            const float* p = fb + r * 132 + lane * 4;
            uint32_t hp[2];
            float rs = 0.f;
            #pragma unroll
            for (int e = 0; e < 2; e++) {
                __nv_bfloat16 h0 = __float2bfloat16(__expf(p[2 * e]));
                __nv_bfloat16 h1 = __float2bfloat16(__expf(p[2 * e + 1]));
                rs += __bfloat162float(h0) + __bfloat162float(h1);
                hp[e] = packbf(h0, h1);
            }
            size_t o = ((size_t)b * NN + m) * NN + n0 + lane * 4;
            *reinterpret_cast<uint2*>(g_pTh + o) = *reinterpret_cast<uint2*>(hp);
            #pragma unroll
            for (int of = 16; of; of >>= 1) rs += __shfl_xor_sync(0xffffffffu, rs, of);
            if (lane == 0) atomicAdd(&g_csum[b * NN + m], rs);
        }
    }
}

// =================================================================
// invert csum -> cinv
// =================================================================
__global__ void inv_k(void) {
    int i = blockIdx.x * blockDim.x + threadIdx.x;
    if (i < BB * NN) g_cinv[i] = 1.0f / g_csum[i];
}

// =================================================================
// AV (P=1,S=3): D[c][m] = v[c]·pT[m]; out = gamma*cinv[m]*D + x
// =================================================================
__global__ __launch_bounds__(256, 2)
void gemm_av_mma(const float* __restrict__ x, const float* __restrict__ gamma,
                 float* __restrict__ out) {
    extern __shared__ __align__(16) char sm[];
    uint32_t su = smem_u32(sm);
    int b = blockIdx.z, m0 = blockIdx.x * 128, c0 = blockIdx.y * 128;
    const __nv_bfloat16* Ah = g_vh  + ((size_t)b * CC + c0) * NN;
    const __nv_bfloat16* Bh = g_pTh + ((size_t)b * NN + m0) * NN;
    float acc[4][4][4];
    run_gemm<1, 3>(su, Ah, (const __nv_bfloat16*)0, NN, Bh, (const __nv_bfloat16*)0, NN, NN / 32, acc);

    float* fb = (float*)sm;
    int tid = threadIdx.x, lane = tid & 31;
    float gm = *gamma;
    for (int h = 0; h < 2; h++) {
        __syncthreads();
        stage_half(fb, h, acc);
        __syncthreads();
        #pragma unroll
        for (int j = 0; j < 8; j++) {
            int r = (tid >> 5) + j * 8;
            int c = c0 + h * 64 + r;
            int m = m0 + lane * 4;
            float4 d = *reinterpret_cast<const float4*>(fb + r * 132 + lane * 4);
            float4 ci = *reinterpret_cast<const float4*>(g_cinv + b * NN + m);
            size_t o = ((size_t)b * CC + c) * NN + m;
            float4 xv = *reinterpret_cast<const float4*>(x + o);
            float4 ov;
            ov.x = gm * ci.x * d.x + xv.x;
            ov.y = gm * ci.y * d.y + xv.y;
            ov.z = gm * ci.z * d.z + xv.z;
            ov.w = gm * ci.w * d.w + xv.w;
            *reinterpret_cast<float4*>(out + o) = ov;
        }
    }
}

// =================================================================
extern "C" void kernel_launch(void* const* d_in, const int* in_sizes, int n_in,
                              void* d_out, int out_size) {
    const float* x     = (const float*)d_in[0];
    const float* Wq    = (const float*)d_in[1];
    const float* bq    = (const float*)d_in[2];
    const float* uq    = (const float*)d_in[3];
    const float* Wk    = (const float*)d_in[4];
    const float* bk    = (const float*)d_in[5];
    const float* uk    = (const float*)d_in[6];
    const float* Wv    = (const float*)d_in[7];
    const float* bv    = (const float*)d_in[8];
    const float* uv    = (const float*)d_in[9];
    const float* gamma = (const float*)d_in[10];
    float* out = (float*)d_out;

    static int inited = 0;
    if (!inited) {
        cudaFuncSetAttribute(proj_qk_mma, cudaFuncAttributeMaxDynamicSharedMemorySize, SMEM_QKP);
        cudaFuncSetAttribute(proj_v_mma,  cudaFuncAttributeMaxDynamicSharedMemorySize, SMEM_PV);
        cudaFuncSetAttribute(gemm_qk_mma, cudaFuncAttributeMaxDynamicSharedMemorySize, SMEM_QKP);
        cudaFuncSetAttribute(gemm_av_mma, cudaFuncAttributeMaxDynamicSharedMemorySize, SMEM_AV);
        inited = 1;
    }

    spectral_k<<<3, 512>>>(Wq, uq, Wk, uk, Wv, uv);
    build_w2k<<<(MR * CC + 255) / 256, 256>>>(Wq, bq, Wk, bk, Wv, bv);
    xsplit_k<<<dim3(NN / 32, CC / 32, BB), dim3(32, 8)>>>(x);
    proj_qk_mma<<<dim3(NN / 128, 1, BB), 256, SMEM_QKP>>>();
    proj_v_mma<<<dim3(NN / 128, CC / 128, BB), 256, SMEM_PV>>>();
    gemm_qk_mma<<<dim3(NN / 128, NN / 128, BB), 256, SMEM_QKP>>>();
    inv_k<<<(BB * NN + 255) / 256, 256>>>();
    gemm_av_mma<<<dim3(NN / 128, CC / 128, BB), 256, SMEM_AV>>>(x, gamma, out);
}